// round 1
// baseline (speedup 1.0000x reference)
#include <cuda_runtime.h>
#include <math.h>

// Problem constants (fixed by the dataset)
#define DIM    2048
#define SEQ    8192
#define CHUNK_LEN 32
#define NCHUNK (SEQ / CHUNK_LEN)   // 256 chunks cover the whole sequence
#define TPB    128                 // threads per partial block
#define DBLK   (TPB * 4)           // 512 dims per block (float4 per thread)
#define GX     (DIM / DBLK)        // 4 dim-blocks

// Scratch for per-chunk partial sums. Written in FULL every launch
// (inactive chunks write zeros), so no zero-init pass is needed and
// the kernel stays deterministic + graph-capturable.
__device__ float g_scratch[NCHUNK * DIM];

__device__ __forceinline__ float sigmoidf_(float x) {
    return 1.0f / (1.0f + expf(-x));
}

// Each block: chunk c (blockIdx.y), dims [blockIdx.x*512, +512).
// partial[c][dim] = sum_{j=0..31} d^(c*32 + j) * emb[idx[S-1-c*32-j]][dim]
__global__ void __launch_bounds__(TPB)
impulse_partial_kernel(const int* __restrict__ idx,
                       const float* __restrict__ emb,
                       const float* __restrict__ ssm_decay)
{
    const int c   = blockIdx.y;
    const int dim = blockIdx.x * DBLK + threadIdx.x * 4;

    const float d = sigmoidf_(ssm_decay[0]);

    // Weight of the newest token in this chunk: d^(c*CHUNK_LEN).
    float w = powf(d, (float)(c * CHUNK_LEN));

    float ax = 0.0f, ay = 0.0f, az = 0.0f, aw = 0.0f;

    if (w > 0.0f) {
        const int tbase = SEQ - 1 - c * CHUNK_LEN;
        #pragma unroll 8
        for (int j = 0; j < CHUNK_LEN; ++j) {
            const int t = tbase - j;
            const long long row = (long long)__ldg(idx + t) * (long long)DIM;
            const float4 x = *reinterpret_cast<const float4*>(emb + row + dim);
            ax = fmaf(w, x.x, ax);
            ay = fmaf(w, x.y, ay);
            az = fmaf(w, x.z, az);
            aw = fmaf(w, x.w, aw);
            w *= d;
        }
    }

    float4 out;
    out.x = ax; out.y = ay; out.z = az; out.w = aw;
    *reinterpret_cast<float4*>(g_scratch + (size_t)c * DIM + dim) = out;
}

// Reduce partials per dim (smallest-magnitude chunks first), scale by (1-d), tanh.
__global__ void __launch_bounds__(256)
impulse_finalize_kernel(const float* __restrict__ ssm_decay,
                        float* __restrict__ out)
{
    const int dim = blockIdx.x * blockDim.x + threadIdx.x;
    if (dim >= DIM) return;

    const float d = sigmoidf_(ssm_decay[0]);

    float s = 0.0f;
    #pragma unroll 8
    for (int c = NCHUNK - 1; c >= 0; --c) {
        s += g_scratch[c * DIM + dim];
    }
    out[dim] = tanhf((1.0f - d) * s);
}

extern "C" void kernel_launch(void* const* d_in, const int* in_sizes, int n_in,
                              void* d_out, int out_size)
{
    const int*   indices   = (const int*)d_in[0];
    const float* embedding = (const float*)d_in[1];
    const float* ssm_decay = (const float*)d_in[2];
    float*       out       = (float*)d_out;

    (void)in_sizes; (void)n_in; (void)out_size;

    dim3 grid(GX, NCHUNK);
    impulse_partial_kernel<<<grid, TPB>>>(indices, embedding, ssm_decay);
    impulse_finalize_kernel<<<DIM / 256, 256>>>(ssm_decay, out);
}

// round 2
// speedup vs baseline: 1.9494x; 1.9494x over previous
#include <cuda_runtime.h>
#include <math.h>

// Problem constants (fixed by the dataset)
#define DIM       2048
#define SEQ       8192
#define CHUNK_LEN 16
#define NCHUNK    (SEQ / CHUNK_LEN)   // 512 chunks cover the whole sequence
#define TPB       128                 // threads per partial block
#define DBLK      (TPB * 4)           // 512 dims per block (float4 per thread)
#define GX        (DIM / DBLK)        // 4 dim-blocks

// Scratch for per-chunk partial sums. ONLY chunks with nonzero weight are
// ever written, and the finalize kernel reads exactly the same set (both
// sides evaluate the identical `powf(d, c*CHUNK_LEN) > 0` predicate), so
// unwritten regions are never read. Active chunks are rewritten with
// identical values every launch -> deterministic, graph-capturable.
__device__ float g_scratch[NCHUNK * DIM];

__device__ __forceinline__ float sigmoidf_(float x) {
    return 1.0f / (1.0f + expf(-x));
}

// Each block: chunk c (blockIdx.y), dims [blockIdx.x*512, +512).
// scratch[c][dim] = sum_{j=0..15} d^(c*16 + j) * emb[idx[S-1-c*16-j]][dim]
__global__ void __launch_bounds__(TPB)
impulse_partial_kernel(const int* __restrict__ idx,
                       const float* __restrict__ emb,
                       const float* __restrict__ ssm_decay)
{
    const int c = blockIdx.y;

    const float d = sigmoidf_(ssm_decay[0]);

    // Weight of the newest token in this chunk: d^(c*CHUNK_LEN).
    float w = powf(d, (float)(c * CHUNK_LEN));
    if (!(w > 0.0f)) return;   // inactive chunk: no work, no write

    const int dim   = blockIdx.x * DBLK + threadIdx.x * 4;
    const int tbase = SEQ - 1 - c * CHUNK_LEN;

    float ax = 0.0f, ay = 0.0f, az = 0.0f, aw = 0.0f;

    #pragma unroll
    for (int j = 0; j < CHUNK_LEN; ++j) {
        const int t = tbase - j;
        const long long row = (long long)__ldg(idx + t) * (long long)DIM;
        const float4 x = *reinterpret_cast<const float4*>(emb + row + dim);
        ax = fmaf(w, x.x, ax);
        ay = fmaf(w, x.y, ay);
        az = fmaf(w, x.z, az);
        aw = fmaf(w, x.w, aw);
        w *= d;
    }

    float4 out;
    out.x = ax; out.y = ay; out.z = az; out.w = aw;
    *reinterpret_cast<float4*>(g_scratch + (size_t)c * DIM + dim) = out;
}

// Sum the active chunks' partials per dim (oldest/smallest first for
// accuracy), scale by (1-d), tanh. Skips chunks the partial kernel skipped.
__global__ void __launch_bounds__(256)
impulse_finalize_kernel(const float* __restrict__ ssm_decay,
                        float* __restrict__ out)
{
    const int dim = blockIdx.x * blockDim.x + threadIdx.x;

    const float d = sigmoidf_(ssm_decay[0]);

    // Find number of active chunks: largest c with powf(d, c*CHUNK_LEN) > 0.
    // Same predicate, same powf, same inputs as the partial kernel -> the
    // read set below exactly matches the write set above.
    int nact = NCHUNK;
    for (int c = 0; c < NCHUNK; ++c) {
        if (!(powf(d, (float)(c * CHUNK_LEN)) > 0.0f)) { nact = c; break; }
    }

    float s = 0.0f;
    for (int c = nact - 1; c >= 0; --c) {   // smallest contributions first
        s += g_scratch[c * DIM + dim];
    }
    out[dim] = tanhf((1.0f - d) * s);
}

extern "C" void kernel_launch(void* const* d_in, const int* in_sizes, int n_in,
                              void* d_out, int out_size)
{
    const int*   indices   = (const int*)d_in[0];
    const float* embedding = (const float*)d_in[1];
    const float* ssm_decay = (const float*)d_in[2];
    float*       out       = (float*)d_out;

    (void)in_sizes; (void)n_in; (void)out_size;

    dim3 grid(GX, NCHUNK);
    impulse_partial_kernel<<<grid, TPB>>>(indices, embedding, ssm_decay);
    impulse_finalize_kernel<<<DIM / 256, 256>>>(ssm_decay, out);
}

// round 3
// speedup vs baseline: 3.1490x; 1.6154x over previous
#include <cuda_runtime.h>
#include <math.h>

// Problem constants (fixed by the dataset)
#define DIM     2048
#define SEQ     8192
#define NBLK    8                 // blocks; each owns DIM/NBLK = 256 dims
#define TPB     512               // 8 token-groups x 64 dim-lanes
#define NLANE   64                // lanes per group; 64 * float4 = 256 dims
#define NGRP    8                 // token groups per block
// Truncation: keep tokens with weight d^t > 2^-33.2 (~1e-10). Tail
// contribution is <= d^ntok/(1-d)*(1-d) ~ 1e-10 relative — far below the
// 1e-3 tolerance and below current fp32 rounding noise.
#define TCUT    33.2f

__device__ __forceinline__ float sigmoidf_(float x) {
    return 1.0f / (1.0f + expf(-x));
}

// out[dim] = tanh( (1-d) * sum_{t=0..ntok-1} d^t * emb[idx[SEQ-1-t]][dim] )
__global__ void __launch_bounds__(TPB)
impulse_fused_kernel(const int* __restrict__ idx,
                     const float* __restrict__ emb,
                     const float* __restrict__ ssm_decay,
                     float* __restrict__ out)
{
    __shared__ float4 red[NGRP - 1][NLANE];

    const int lane = threadIdx.x & (NLANE - 1);   // dim lane within block
    const int tg   = threadIdx.x >> 6;            // token group 0..7

    const int dim = blockIdx.x * (NLANE * 4) + lane * 4;

    const float d   = sigmoidf_(ssm_decay[0]);
    const float l2d = log2f(d);                   // < 0 since 0 < d < 1

    // Number of tokens (from the end) whose weight d^t stays above 2^-TCUT.
    int ntok = (int)(TCUT / (-l2d)) + 1;
    if (ntok > SEQ) ntok = SEQ;

    // Per-group geometric weights: token t = tg, tg+8, tg+16, ...
    float w = exp2f((float)tg * l2d);             // d^tg
    const float wstep = exp2f((float)NGRP * l2d); // d^8

    float ax = 0.0f, ay = 0.0f, az = 0.0f, aw = 0.0f;

    #pragma unroll 4
    for (int t = tg; t < ntok; t += NGRP) {
        const long long row =
            (long long)__ldg(idx + (SEQ - 1 - t)) * (long long)DIM;
        const float4 x = *reinterpret_cast<const float4*>(emb + row + dim);
        ax = fmaf(w, x.x, ax);
        ay = fmaf(w, x.y, ay);
        az = fmaf(w, x.z, az);
        aw = fmaf(w, x.w, aw);
        w *= wstep;
    }

    // Cross-group reduction in shared memory (fixed order -> deterministic).
    if (tg > 0) {
        float4 v; v.x = ax; v.y = ay; v.z = az; v.w = aw;
        red[tg - 1][lane] = v;
    }
    __syncthreads();

    if (tg == 0) {
        #pragma unroll
        for (int g = 0; g < NGRP - 1; ++g) {
            const float4 v = red[g][lane];
            ax += v.x; ay += v.y; az += v.z; aw += v.w;
        }
        const float s = 1.0f - d;
        float4 o;
        o.x = tanhf(s * ax);
        o.y = tanhf(s * ay);
        o.z = tanhf(s * az);
        o.w = tanhf(s * aw);
        *reinterpret_cast<float4*>(out + dim) = o;
    }
}

extern "C" void kernel_launch(void* const* d_in, const int* in_sizes, int n_in,
                              void* d_out, int out_size)
{
    const int*   indices   = (const int*)d_in[0];
    const float* embedding = (const float*)d_in[1];
    const float* ssm_decay = (const float*)d_in[2];
    float*       out       = (float*)d_out;

    (void)in_sizes; (void)n_in; (void)out_size;

    impulse_fused_kernel<<<NBLK, TPB>>>(indices, embedding, ssm_decay, out);
}

// round 4
// speedup vs baseline: 3.1643x; 1.0048x over previous
#include <cuda_runtime.h>
#include <math.h>

// Problem constants (fixed by the dataset)
#define DIM     2048
#define SEQ     8192
#define NBLK    8                 // blocks; each owns DIM/NBLK = 256 dims
#define TPB     512               // 8 token-groups x 64 dim-lanes
#define NLANE   64                // lanes per group; 64 * float4 = 256 dims
#define NGRP    8                 // token groups per block
#define TILE    512               // tokens staged per smem tile
// Truncation: keep tokens with weight d^t > 2^-26.6 (~1e-8). Truncated tail
// contributes ~1e-8 of the state's std — worst-case per-element relative
// error ~3e-5, 30x under the 1e-3 tolerance.
#define TCUT    26.6f

__device__ __forceinline__ float sigmoidf_(float x) {
    return 1.0f / (1.0f + expf(-x));
}

// out[dim] = tanh( (1-d) * sum_{t=0..ntok-1} d^t * emb[idx[SEQ-1-t]][dim] )
__global__ void __launch_bounds__(TPB)
impulse_fused_kernel(const int* __restrict__ idx,
                     const float* __restrict__ emb,
                     const float* __restrict__ ssm_decay,
                     float* __restrict__ out)
{
    __shared__ int    s_row[TILE];            // precomputed row offsets
    __shared__ float4 red[NGRP - 1][NLANE];

    const int lane = threadIdx.x & (NLANE - 1);   // dim lane within block
    const int tg   = threadIdx.x >> 6;            // token group 0..7

    const int dim = blockIdx.x * (NLANE * 4) + lane * 4;

    const float d   = sigmoidf_(ssm_decay[0]);
    const float l2d = log2f(d);                   // < 0 since 0 < d < 1

    // Number of newest tokens whose weight d^t stays above 2^-TCUT.
    int ntok = (int)(TCUT / (-l2d)) + 1;
    if (ntok > SEQ) ntok = SEQ;

    const float wstep = exp2f((float)NGRP * l2d); // d^8

    float ax = 0.0f, ay = 0.0f, az = 0.0f, aw = 0.0f;

    for (int base = 0; base < ntok; base += TILE) {
        const int cnt = min(TILE, ntok - base);

        // Stage row offsets: all index loads fly in parallel.
        if (base > 0) __syncthreads();            // protect smem reuse
        for (int t = (int)threadIdx.x; t < cnt; t += TPB)
            s_row[t] = __ldg(idx + (SEQ - 1 - base - t)) * DIM;
        __syncthreads();

        // d^(base+tg): exact restart per tile keeps multi-tile runs correct.
        float w = exp2f((float)(base + tg) * l2d);

        #pragma unroll 4
        for (int t = tg; t < cnt; t += NGRP) {
            const float4 x =
                *reinterpret_cast<const float4*>(emb + (long long)s_row[t] + dim);
            ax = fmaf(w, x.x, ax);
            ay = fmaf(w, x.y, ay);
            az = fmaf(w, x.z, az);
            aw = fmaf(w, x.w, aw);
            w *= wstep;
        }
    }

    // Cross-group reduction in shared memory (fixed order -> deterministic).
    __syncthreads();                              // s_row no longer needed
    if (tg > 0) {
        float4 v; v.x = ax; v.y = ay; v.z = az; v.w = aw;
        red[tg - 1][lane] = v;
    }
    __syncthreads();

    if (tg == 0) {
        #pragma unroll
        for (int g = 0; g < NGRP - 1; ++g) {
            const float4 v = red[g][lane];
            ax += v.x; ay += v.y; az += v.z; aw += v.w;
        }
        const float s = 1.0f - d;
        float4 o;
        o.x = tanhf(s * ax);
        o.y = tanhf(s * ay);
        o.z = tanhf(s * az);
        o.w = tanhf(s * aw);
        *reinterpret_cast<float4*>(out + dim) = o;
    }
}

extern "C" void kernel_launch(void* const* d_in, const int* in_sizes, int n_in,
                              void* d_out, int out_size)
{
    const int*   indices   = (const int*)d_in[0];
    const float* embedding = (const float*)d_in[1];
    const float* ssm_decay = (const float*)d_in[2];
    float*       out       = (float*)d_out;

    (void)in_sizes; (void)n_in; (void)out_size;

    impulse_fused_kernel<<<NBLK, TPB>>>(indices, embedding, ssm_decay, out);
}